// round 9
// baseline (speedup 1.0000x reference)
#include <cuda_runtime.h>
#include <math.h>
#include <stdint.h>

#define TT 2048
#define HH 1024
#define FF 1024
#define EE 8

// ---------------- scratch (device globals; no allocation allowed) ----------
__device__ int   g_cnt[EE];
__device__ int   g_tok[EE][TT];
__device__ float g_wt [EE][TT];
__device__ float g_act[EE][TT][FF];   // routed silu(g)*u activations (64 MB)
__device__ float g_sact[TT][FF];      // shared-expert activations (8 MB)

// ---------------- helpers ---------------------------------------------------
__device__ __forceinline__ uint32_t f2tf32(float f) {
    uint32_t u;
    asm("cvt.rna.tf32.f32 %0, %1;" : "=r"(u) : "f"(f));
    return u;
}
__device__ __forceinline__ uint4 cvt4(float4 v) {
    return make_uint4(f2tf32(v.x), f2tf32(v.y), f2tf32(v.z), f2tf32(v.w));
}
__device__ __forceinline__ uint32_t smem_u32(const void* p) {
    uint32_t a;
    asm("{ .reg .u64 t; cvta.to.shared.u64 t, %1; cvt.u32.u64 %0, t; }"
        : "=r"(a) : "l"(p));
    return a;
}
__device__ __forceinline__ void mma8(float* c, const uint32_t* a, const uint32_t* b) {
    asm volatile(
        "mma.sync.aligned.m16n8k8.row.col.f32.tf32.tf32.f32 "
        "{%0,%1,%2,%3}, {%4,%5,%6,%7}, {%8,%9}, {%0,%1,%2,%3};"
        : "+f"(c[0]), "+f"(c[1]), "+f"(c[2]), "+f"(c[3])
        : "r"(a[0]), "r"(a[1]), "r"(a[2]), "r"(a[3]), "r"(b[0]), "r"(b[1]));
}
__device__ __forceinline__ void ldsm4(uint32_t* r, uint32_t addr) {
    asm volatile("ldmatrix.sync.aligned.m8n8.x4.shared.b16 {%0,%1,%2,%3}, [%4];"
        : "=r"(r[0]), "=r"(r[1]), "=r"(r[2]), "=r"(r[3]) : "r"(addr));
}
__device__ __forceinline__ void mbar_init(uint32_t a, uint32_t cnt) {
    asm volatile("mbarrier.init.shared.b64 [%0], %1;" :: "r"(a), "r"(cnt) : "memory");
}
__device__ __forceinline__ void mbar_arrive(uint32_t a) {
    asm volatile("mbarrier.arrive.shared.b64 _, [%0];" :: "r"(a) : "memory");
}
__device__ __forceinline__ void mbar_wait(uint32_t a, uint32_t parity) {
    uint32_t done;
    asm volatile("{\n\t.reg .pred p;\n\t"
                 "mbarrier.try_wait.parity.acquire.cta.shared::cta.b64 p, [%1], %2;\n\t"
                 "selp.b32 %0, 1, 0, p;\n\t}"
                 : "=r"(done) : "r"(a), "r"(parity) : "memory");
    if (!done) {
        asm volatile("{\n\t.reg .pred P1;\n\t"
                     "WL_%=:\n\t"
                     "mbarrier.try_wait.parity.acquire.cta.shared::cta.b64 P1, [%0], %1, 0x989680;\n\t"
                     "@P1 bra.uni WD_%=;\n\t"
                     "bra.uni WL_%=;\n\t"
                     "WD_%=:\n\t}"
                     :: "r"(a), "r"(parity) : "memory");
    }
}

// A rows padded to 36 floats (144B) -> LDSM/STS conflict-free.
#define LDR 36
// gateup stage: A 256x36x4=36864 | Bg 32x72x4=9216 | Bu 9216 -> 55296
#define GU_STAGE 55296
#define GU_BG    36864
#define GU_BU    46080
#define GU_MBAR  165888   // full[3] @ +0, empty[3] @ +24
#define GU_BYTES 165952
// down stage: A 36864 | B 32x136x4=17408 -> 54272
#define DN_STAGE 54272
#define DN_B     36864
#define DN_MBAR  162816
#define DN_BYTES 162880

// ---------------- init ------------------------------------------------------
__global__ void init_kernel(float* __restrict__ out, int out_size) {
    int i = blockIdx.x * blockDim.x + threadIdx.x;
    if (i < EE) g_cnt[i] = 0;
    int tail = out_size - TT * HH;
    if (i < tail) out[TT * HH + i] = 0.0f;
}

// ---------------- router ----------------------------------------------------
__global__ void router_kernel(const float* __restrict__ x,
                              const float* __restrict__ wg) {
    int warp = (blockIdx.x * blockDim.x + threadIdx.x) >> 5;
    int lane = threadIdx.x & 31;
    if (warp >= TT) return;
    const float* xr = x + (size_t)warp * HH;

    float acc[EE];
#pragma unroll
    for (int e = 0; e < EE; e++) acc[e] = 0.0f;
    for (int h = lane; h < HH; h += 32) {
        float xv = xr[h];
        const float4* w4 = (const float4*)(wg + (size_t)h * EE);
        float4 a = w4[0], b = w4[1];
        acc[0] += xv * a.x; acc[1] += xv * a.y;
        acc[2] += xv * a.z; acc[3] += xv * a.w;
        acc[4] += xv * b.x; acc[5] += xv * b.y;
        acc[6] += xv * b.z; acc[7] += xv * b.w;
    }
#pragma unroll
    for (int e = 0; e < EE; e++)
#pragma unroll
        for (int o = 16; o > 0; o >>= 1)
            acc[e] += __shfl_xor_sync(0xffffffffu, acc[e], o);

    if (lane == 0) {
        int i0 = 0; float v0 = acc[0];
#pragma unroll
        for (int e = 1; e < EE; e++) if (acc[e] > v0) { v0 = acc[e]; i0 = e; }
        int i1 = -1; float v1 = -INFINITY;
#pragma unroll
        for (int e = 0; e < EE; e++) {
            if (e == i0) continue;
            if (acc[e] > v1) { v1 = acc[e]; i1 = e; }
        }
        float ex = expf(v1 - v0);
        float inv = 1.0f / (1.0f + ex);
        int p0 = atomicAdd(&g_cnt[i0], 1);
        g_tok[i0][p0] = warp; g_wt[i0][p0] = inv;
        int p1 = atomicAdd(&g_cnt[i1], 1);
        g_tok[i1][p1] = warp; g_wt[i1][p1] = ex * inv;
    }
}

// ---------------- fused gate+up GEMM: 256x64, warp-specialized, 3 stages ---
// Warps 0-7 consumers (4M x 2N, warp tile 64x32 per matrix), 8-11 producers.
template <bool GATHER>
__global__ __launch_bounds__(384, 1)
void gemm_gateup(const float* __restrict__ X,
                 const float* __restrict__ Wg_all,
                 const float* __restrict__ Wu_all) {
    const int e  = GATHER ? blockIdx.z : 0;
    const int M  = GATHER ? g_cnt[e] : TT;
    const int m0 = blockIdx.y * 256;
    if (m0 >= M) return;
    const int n0 = blockIdx.x * 64;

    extern __shared__ char smem[];
    const uint32_t sbase = smem_u32(smem);
    const int tid = threadIdx.x;
    const int wid = tid >> 5, lane = tid & 31;

    const uint32_t mb_full  = sbase + GU_MBAR;
    const uint32_t mb_empty = sbase + GU_MBAR + 24;
    if (tid == 0) {
#pragma unroll
        for (int s = 0; s < 3; s++) {
            mbar_init(mb_full  + 8 * s, 4);   // 4 producer warps
            mbar_init(mb_empty + 8 * s, 8);   // 8 consumer warps
        }
    }
    __syncthreads();

    if (wid < 8) {
        // ================= consumer =================
        const int wm = wid >> 1, wn = wid & 1;
        const int grp = lane >> 2, qid = lane & 3;
        uint32_t aoff[4];
#pragma unroll
        for (int mt = 0; mt < 4; mt++)
            aoff[mt] = ((wm * 64 + mt * 16 + (lane & 15)) * LDR + ((lane & 16) ? 4 : 0)) * 4;

        float cg[4][4][4], cu[4][4][4];
#pragma unroll
        for (int mt = 0; mt < 4; mt++)
#pragma unroll
            for (int nt = 0; nt < 4; nt++)
#pragma unroll
                for (int i = 0; i < 4; i++) { cg[mt][nt][i] = 0.0f; cu[mt][nt][i] = 0.0f; }

        int s = 0, ph = 0;
        for (int c = 0; c < 32; c++) {
            mbar_wait(mb_full + 8 * s, ph);
            const uint32_t Ab = sbase + s * GU_STAGE;
            const char* Gb = smem + s * GU_STAGE + GU_BG;
            const char* Ub = smem + s * GU_STAGE + GU_BU;
#pragma unroll
            for (int ks = 0; ks < 32; ks += 8) {
                uint32_t a[4][4];
#pragma unroll
                for (int mt = 0; mt < 4; mt++)
                    ldsm4(a[mt], Ab + aoff[mt] + ks * 4);
#pragma unroll
                for (int nt = 0; nt < 4; nt++) {
                    int cb = wn * 32 + nt * 8 + grp;
                    uint32_t r0 = (uint32_t)(ks + qid) * 288 + cb * 4;
                    uint32_t bg_[2], bu_[2];
                    bg_[0] = *(const uint32_t*)(Gb + r0);
                    bg_[1] = *(const uint32_t*)(Gb + r0 + 4 * 288);
#pragma unroll
                    for (int mt = 0; mt < 4; mt++) mma8(cg[mt][nt], a[mt], bg_);
                    bu_[0] = *(const uint32_t*)(Ub + r0);
                    bu_[1] = *(const uint32_t*)(Ub + r0 + 4 * 288);
#pragma unroll
                    for (int mt = 0; mt < 4; mt++) mma8(cu[mt][nt], a[mt], bu_);
                }
            }
            __syncwarp();
            if (lane == 0) mbar_arrive(mb_empty + 8 * s);
            if (++s == 3) { s = 0; ph ^= 1; }
        }

        // epilogue: silu(g)*u
#pragma unroll
        for (int mt = 0; mt < 4; mt++) {
#pragma unroll
            for (int half = 0; half < 2; half++) {
                int m = m0 + wm * 64 + mt * 16 + grp + half * 8;
                if (m >= M) continue;
                float* orow = GATHER ? &g_act[e][m][0] : &g_sact[m][0];
#pragma unroll
                for (int nt = 0; nt < 4; nt++) {
                    int c0 = n0 + wn * 32 + nt * 8 + 2 * qid;
                    float g0 = cg[mt][nt][half * 2 + 0], u0 = cu[mt][nt][half * 2 + 0];
                    float g1 = cg[mt][nt][half * 2 + 1], u1 = cu[mt][nt][half * 2 + 1];
                    float2 o;
                    o.x = (g0 / (1.0f + expf(-g0))) * u0;
                    o.y = (g1 / (1.0f + expf(-g1))) * u1;
                    *(float2*)&orow[c0] = o;
                }
            }
        }
    } else {
        // ================= producer =================
        const int ptid = tid - 256;          // 0..127
        const int base = ptid >> 2;          // 0..31
        const int q    = ptid & 3;
        const int akof = q * 8;              // A col offset (floats)

        const float* ap[8];
#pragma unroll
        for (int i = 0; i < 8; i++) {
            int r = m0 + base + 32 * i;
            if (r < M) {
                int tok = GATHER ? g_tok[e][r] : r;
                ap[i] = X + (size_t)tok * HH + akof;
            } else ap[i] = nullptr;
        }
        const float* gptr = Wg_all + (GATHER ? (size_t)e * HH * FF : 0)
                            + (size_t)base * FF + n0 + q * 4;
        const float* uptr = Wu_all + (GATHER ? (size_t)e * HH * FF : 0)
                            + (size_t)base * FF + n0 + q * 4;

        int s = 0, ph = 1;   // first empty-wait passes immediately
        for (int c = 0; c < 32; c++) {
            const int kk = c * 32;
            float4 av[8][2], gv[4], uv[4];
#pragma unroll
            for (int i = 0; i < 8; i++) {
                av[i][0] = ap[i] ? *(const float4*)(ap[i] + kk)     : make_float4(0,0,0,0);
                av[i][1] = ap[i] ? *(const float4*)(ap[i] + kk + 4) : make_float4(0,0,0,0);
            }
#pragma unroll
            for (int i = 0; i < 4; i++) {
                gv[i] = *(const float4*)(gptr + (size_t)kk * FF + i * 16);
                uv[i] = *(const float4*)(uptr + (size_t)kk * FF + i * 16);
            }
            mbar_wait(mb_empty + 8 * s, ph);
            char* Ast = smem + s * GU_STAGE;
#pragma unroll
            for (int i = 0; i < 8; i++) {
                int row = base + 32 * i;
                *(uint4*)(Ast + (row * LDR + akof) * 4)     = cvt4(av[i][0]);
                *(uint4*)(Ast + (row * LDR + akof + 4) * 4) = cvt4(av[i][1]);
            }
            char* Gst = Ast + GU_BG;
            char* Ust = Ast + GU_BU;
#pragma unroll
            for (int i = 0; i < 4; i++) {
                uint32_t off = (uint32_t)base * 288 + (q * 4 + i * 16) * 4;
                *(uint4*)(Gst + off) = cvt4(gv[i]);
                *(uint4*)(Ust + off) = cvt4(uv[i]);
            }
            __syncwarp();
            if (lane == 0) mbar_arrive(mb_full + 8 * s);
            if (++s == 3) { s = 0; ph ^= 1; }
        }
    }
}

// ---------------- down-proj GEMM: 256x128, warp-specialized, 3 stages ------
// Consumers 4M x 2N, warp tile 64x64.
template <bool EXPERT>
__global__ __launch_bounds__(384, 1)
void gemm_down(const float* __restrict__ Wd_all,
               float* __restrict__ out) {
    const int e  = EXPERT ? blockIdx.z : 0;
    const int M  = EXPERT ? g_cnt[e] : TT;
    const int m0 = blockIdx.y * 256;
    if (m0 >= M) return;
    const int n0 = blockIdx.x * 128;

    extern __shared__ char smem[];
    const uint32_t sbase = smem_u32(smem);
    const int tid = threadIdx.x;
    const int wid = tid >> 5, lane = tid & 31;

    const uint32_t mb_full  = sbase + DN_MBAR;
    const uint32_t mb_empty = sbase + DN_MBAR + 24;
    if (tid == 0) {
#pragma unroll
        for (int s = 0; s < 3; s++) {
            mbar_init(mb_full  + 8 * s, 4);
            mbar_init(mb_empty + 8 * s, 8);
        }
    }
    __syncthreads();

    const float* Asrc = EXPERT ? &g_act[e][0][0] : &g_sact[0][0];

    if (wid < 8) {
        // ================= consumer =================
        const int wm = wid >> 1, wn = wid & 1;
        const int grp = lane >> 2, qid = lane & 3;
        uint32_t aoff[4];
#pragma unroll
        for (int mt = 0; mt < 4; mt++)
            aoff[mt] = ((wm * 64 + mt * 16 + (lane & 15)) * LDR + ((lane & 16) ? 4 : 0)) * 4;

        float cc[4][8][4];
#pragma unroll
        for (int mt = 0; mt < 4; mt++)
#pragma unroll
            for (int nt = 0; nt < 8; nt++)
#pragma unroll
                for (int i = 0; i < 4; i++) cc[mt][nt][i] = 0.0f;

        int s = 0, ph = 0;
        for (int c = 0; c < 32; c++) {
            mbar_wait(mb_full + 8 * s, ph);
            const uint32_t Ab = sbase + s * DN_STAGE;
            const char* Bb = smem + s * DN_STAGE + DN_B;
#pragma unroll
            for (int ks = 0; ks < 32; ks += 8) {
                uint32_t a[4][4];
#pragma unroll
                for (int mt = 0; mt < 4; mt++)
                    ldsm4(a[mt], Ab + aoff[mt] + ks * 4);
#pragma unroll
                for (int nt = 0; nt < 8; nt++) {
                    int cb = wn * 64 + nt * 8 + grp;
                    uint32_t r0 = (uint32_t)(ks + qid) * 544 + cb * 4;
                    uint32_t b_[2];
                    b_[0] = *(const uint32_t*)(Bb + r0);
                    b_[1] = *(const uint32_t*)(Bb + r0 + 4 * 544);
#pragma unroll
                    for (int mt = 0; mt < 4; mt++) mma8(cc[mt][nt], a[mt], b_);
                }
            }
            __syncwarp();
            if (lane == 0) mbar_arrive(mb_empty + 8 * s);
            if (++s == 3) { s = 0; ph ^= 1; }
        }

#pragma unroll
        for (int mt = 0; mt < 4; mt++) {
#pragma unroll
            for (int half = 0; half < 2; half++) {
                int m = m0 + wm * 64 + mt * 16 + grp + half * 8;
                if (m >= M) continue;
                if (EXPERT) {
                    int tok = g_tok[e][m];
                    float w = g_wt[e][m];
                    float* orow = out + (size_t)tok * HH;
#pragma unroll
                    for (int nt = 0; nt < 8; nt++) {
                        int c0 = n0 + wn * 64 + nt * 8 + 2 * qid;
                        atomicAdd(&orow[c0],     w * cc[mt][nt][half * 2 + 0]);
                        atomicAdd(&orow[c0 + 1], w * cc[mt][nt][half * 2 + 1]);
                    }
                } else {
                    float* orow = out + (size_t)m * HH;
#pragma unroll
                    for (int nt = 0; nt < 8; nt++) {
                        int c0 = n0 + wn * 64 + nt * 8 + 2 * qid;
                        float2 o = make_float2(cc[mt][nt][half * 2 + 0],
                                               cc[mt][nt][half * 2 + 1]);
                        *(float2*)&orow[c0] = o;
                    }
                }
            }
        }
    } else {
        // ================= producer =================
        const int ptid = tid - 256;
        const int base = ptid >> 2;
        const int q    = ptid & 3;
        const int akof = q * 8;

        const float* ap[8];
#pragma unroll
        for (int i = 0; i < 8; i++) {
            int r = m0 + base + 32 * i;
            ap[i] = (r < M) ? (Asrc + (size_t)r * FF + akof) : nullptr;
        }
        const float* wptr = Wd_all + (EXPERT ? (size_t)e * FF * HH : 0)
                            + (size_t)base * HH + n0 + q * 4;

        int s = 0, ph = 1;
        for (int c = 0; c < 32; c++) {
            const int kk = c * 32;
            float4 av[8][2], bv[8];
#pragma unroll
            for (int i = 0; i < 8; i++) {
                av[i][0] = ap[i] ? *(const float4*)(ap[i] + kk)     : make_float4(0,0,0,0);
                av[i][1] = ap[i] ? *(const float4*)(ap[i] + kk + 4) : make_float4(0,0,0,0);
            }
#pragma unroll
            for (int i = 0; i < 8; i++)
                bv[i] = *(const float4*)(wptr + (size_t)kk * HH + i * 16);

            mbar_wait(mb_empty + 8 * s, ph);
            char* Ast = smem + s * DN_STAGE;
#pragma unroll
            for (int i = 0; i < 8; i++) {
                int row = base + 32 * i;
                *(uint4*)(Ast + (row * LDR + akof) * 4)     = cvt4(av[i][0]);
                *(uint4*)(Ast + (row * LDR + akof + 4) * 4) = cvt4(av[i][1]);
            }
            char* Bst = Ast + DN_B;
#pragma unroll
            for (int i = 0; i < 8; i++) {
                uint32_t off = (uint32_t)base * 544 + (q * 4 + i * 16) * 4;
                *(uint4*)(Bst + off) = cvt4(bv[i]);
            }
            __syncwarp();
            if (lane == 0) mbar_arrive(mb_full + 8 * s);
            if (++s == 3) { s = 0; ph ^= 1; }
        }
    }
}

// ---------------- launch ---------------------------------------------------
extern "C" void kernel_launch(void* const* d_in, const int* in_sizes, int n_in,
                              void* d_out, int out_size) {
    const float* x   = (const float*)d_in[0];
    const float* wg  = (const float*)d_in[1];
    const float* wgp = (const float*)d_in[2];
    const float* wup = (const float*)d_in[3];
    const float* wdp = (const float*)d_in[4];
    const float* wsg = (const float*)d_in[5];
    const float* wsu = (const float*)d_in[6];
    const float* wsd = (const float*)d_in[7];
    float* out = (float*)d_out;

    cudaFuncSetAttribute(gemm_gateup<false>, cudaFuncAttributeMaxDynamicSharedMemorySize, GU_BYTES);
    cudaFuncSetAttribute(gemm_gateup<true>,  cudaFuncAttributeMaxDynamicSharedMemorySize, GU_BYTES);
    cudaFuncSetAttribute(gemm_down<false>,   cudaFuncAttributeMaxDynamicSharedMemorySize, DN_BYTES);
    cudaFuncSetAttribute(gemm_down<true>,    cudaFuncAttributeMaxDynamicSharedMemorySize, DN_BYTES);

    int tail = out_size - TT * HH;
    int init_n = (tail > EE ? tail : EE);
    init_kernel<<<(init_n + 255) / 256, 256>>>(out, out_size);

    router_kernel<<<TT / 8, 256>>>(x, wg);

    dim3 gs1(FF / 64, TT / 256, 1);
    gemm_gateup<false><<<gs1, 384, GU_BYTES>>>(x, wsg, wsu);

    dim3 ge1(FF / 64, TT / 256, EE);
    gemm_gateup<true><<<ge1, 384, GU_BYTES>>>(x, wgp, wup);

    dim3 gs2(HH / 128, TT / 256, 1);
    gemm_down<false><<<gs2, 384, DN_BYTES>>>(wsd, out);   // plain store: initializes out

    dim3 ge2(HH / 128, TT / 256, EE);
    gemm_down<true><<<ge2, 384, DN_BYTES>>>(wdp, out);    // weighted atomicAdd combine
}

// round 11
// speedup vs baseline: 1.3757x; 1.3757x over previous
#include <cuda_runtime.h>
#include <cuda_fp16.h>
#include <math.h>
#include <stdint.h>

#define TT 2048
#define HH 1024
#define FF 1024
#define EE 8

// ---------------- scratch (device globals; no allocation allowed) ----------
__device__ int   g_cnt[EE];
__device__ int   g_tok[EE][TT];
__device__ float g_wt [EE][TT];
__device__ float g_act[EE][TT][FF];   // routed silu(g)*u activations (64 MB)
__device__ float g_sact[TT][FF];      // shared-expert activations (8 MB)

// ---------------- helpers ---------------------------------------------------
__device__ __forceinline__ uint32_t h2(float x, float y) {
    __half2 h = __floats2half2_rn(x, y);
    return *(uint32_t*)&h;
}
__device__ __forceinline__ uint4 cvt8(float4 a, float4 b) {
    return make_uint4(h2(a.x, a.y), h2(a.z, a.w), h2(b.x, b.y), h2(b.z, b.w));
}
__device__ __forceinline__ uint2 cvt4h(float4 v) {
    return make_uint2(h2(v.x, v.y), h2(v.z, v.w));
}
__device__ __forceinline__ uint32_t smem_u32(const void* p) {
    uint32_t a;
    asm("{ .reg .u64 t; cvta.to.shared.u64 t, %1; cvt.u32.u64 %0, t; }"
        : "=r"(a) : "l"(p));
    return a;
}
__device__ __forceinline__ void mma16(float* c, const uint32_t* a, const uint32_t* b) {
    asm volatile(
        "mma.sync.aligned.m16n8k16.row.col.f32.f16.f16.f32 "
        "{%0,%1,%2,%3}, {%4,%5,%6,%7}, {%8,%9}, {%0,%1,%2,%3};"
        : "+f"(c[0]), "+f"(c[1]), "+f"(c[2]), "+f"(c[3])
        : "r"(a[0]), "r"(a[1]), "r"(a[2]), "r"(a[3]), "r"(b[0]), "r"(b[1]));
}
__device__ __forceinline__ void ldsm4(uint32_t* r, uint32_t addr) {
    asm volatile("ldmatrix.sync.aligned.m8n8.x4.shared.b16 {%0,%1,%2,%3}, [%4];"
        : "=r"(r[0]), "=r"(r[1]), "=r"(r[2]), "=r"(r[3]) : "r"(addr));
}
__device__ __forceinline__ void ldsm4t(uint32_t* r, uint32_t addr) {
    asm volatile("ldmatrix.sync.aligned.m8n8.x4.trans.shared.b16 {%0,%1,%2,%3}, [%4];"
        : "=r"(r[0]), "=r"(r[1]), "=r"(r[2]), "=r"(r[3]) : "r"(addr));
}
__device__ __forceinline__ void mbar_init(uint32_t a, uint32_t cnt) {
    asm volatile("mbarrier.init.shared.b64 [%0], %1;" :: "r"(a), "r"(cnt) : "memory");
}
__device__ __forceinline__ void mbar_arrive(uint32_t a) {
    asm volatile("mbarrier.arrive.shared.b64 _, [%0];" :: "r"(a) : "memory");
}
__device__ __forceinline__ void mbar_wait(uint32_t a, uint32_t parity) {
    uint32_t done;
    asm volatile("{\n\t.reg .pred p;\n\t"
                 "mbarrier.try_wait.parity.acquire.cta.shared::cta.b64 p, [%1], %2;\n\t"
                 "selp.b32 %0, 1, 0, p;\n\t}"
                 : "=r"(done) : "r"(a), "r"(parity) : "memory");
    if (!done) {
        asm volatile("{\n\t.reg .pred P1;\n\t"
                     "WL_%=:\n\t"
                     "mbarrier.try_wait.parity.acquire.cta.shared::cta.b64 P1, [%0], %1, 0x989680;\n\t"
                     "@P1 bra.uni WD_%=;\n\t"
                     "bra.uni WL_%=;\n\t"
                     "WD_%=:\n\t}"
                     :: "r"(a), "r"(parity) : "memory");
    }
}

// A rows: 32 fp16 padded to 80B (16B-aligned, LDSM conflict-free: 80m%128 distinct)
#define ALDR 80
// B gateup rows: 64 fp16 padded to 144B (144k%128 = 16k distinct)
#define GBR 144
// B down rows: 128 fp16 padded to 272B (272k%128 = 16k distinct)
#define DBR 272
#define NSTAGE 4

// gateup stage: A 128x80=10240 | Bg 32x144=4608 | Bu 4608 -> 19456
#define GU_STAGE 19456
#define GU_BG    10240
#define GU_BU    14848
#define GU_MBAR  77824    // full[4] @ +0, empty[4] @ +32
#define GU_BYTES 77888
// down stage: A 10240 | B 32x272=8704 -> 18944
#define DN_STAGE 18944
#define DN_B     10240
#define DN_MBAR  75776
#define DN_BYTES 75840

// ---------------- init ------------------------------------------------------
__global__ void init_kernel(float* __restrict__ out, int out_size) {
    int i = blockIdx.x * blockDim.x + threadIdx.x;
    if (i < EE) g_cnt[i] = 0;
    int tail = out_size - TT * HH;
    if (i < tail) out[TT * HH + i] = 0.0f;
}

// ---------------- router ----------------------------------------------------
__global__ void router_kernel(const float* __restrict__ x,
                              const float* __restrict__ wg) {
    int warp = (blockIdx.x * blockDim.x + threadIdx.x) >> 5;
    int lane = threadIdx.x & 31;
    if (warp >= TT) return;
    const float* xr = x + (size_t)warp * HH;

    float acc[EE];
#pragma unroll
    for (int e = 0; e < EE; e++) acc[e] = 0.0f;
    for (int h = lane; h < HH; h += 32) {
        float xv = xr[h];
        const float4* w4 = (const float4*)(wg + (size_t)h * EE);
        float4 a = w4[0], b = w4[1];
        acc[0] += xv * a.x; acc[1] += xv * a.y;
        acc[2] += xv * a.z; acc[3] += xv * a.w;
        acc[4] += xv * b.x; acc[5] += xv * b.y;
        acc[6] += xv * b.z; acc[7] += xv * b.w;
    }
#pragma unroll
    for (int e = 0; e < EE; e++)
#pragma unroll
        for (int o = 16; o > 0; o >>= 1)
            acc[e] += __shfl_xor_sync(0xffffffffu, acc[e], o);

    if (lane == 0) {
        int i0 = 0; float v0 = acc[0];
#pragma unroll
        for (int e = 1; e < EE; e++) if (acc[e] > v0) { v0 = acc[e]; i0 = e; }
        int i1 = -1; float v1 = -INFINITY;
#pragma unroll
        for (int e = 0; e < EE; e++) {
            if (e == i0) continue;
            if (acc[e] > v1) { v1 = acc[e]; i1 = e; }
        }
        float ex = expf(v1 - v0);
        float inv = 1.0f / (1.0f + ex);
        int p0 = atomicAdd(&g_cnt[i0], 1);
        g_tok[i0][p0] = warp; g_wt[i0][p0] = inv;
        int p1 = atomicAdd(&g_cnt[i1], 1);
        g_tok[i1][p1] = warp; g_wt[i1][p1] = ex * inv;
    }
}

// ---------------- fused gate+up GEMM: fp16 mma, warp-specialized, 4 stages -
// Block 128(M) x 64(N), BK=32. Warps 0-7 consumers (4M x 2N, warp 32x32 per
// matrix), warps 8-11 producers. A smem [m][k] fp16, B smem [k][n] fp16
// consumed via ldmatrix.trans.
template <bool GATHER>
__global__ __launch_bounds__(384, 1)
void gemm_gateup(const float* __restrict__ X,
                 const float* __restrict__ Wg_all,
                 const float* __restrict__ Wu_all) {
    const int e  = GATHER ? blockIdx.z : 0;
    const int M  = GATHER ? g_cnt[e] : TT;
    const int m0 = blockIdx.y * 128;
    if (m0 >= M) return;
    const int n0 = blockIdx.x * 64;

    extern __shared__ char smem[];
    const uint32_t sbase = smem_u32(smem);
    const int tid = threadIdx.x;
    const int wid = tid >> 5, lane = tid & 31;

    const uint32_t mb_full  = sbase + GU_MBAR;
    const uint32_t mb_empty = sbase + GU_MBAR + 32;
    if (tid == 0) {
#pragma unroll
        for (int s = 0; s < NSTAGE; s++) {
            mbar_init(mb_full  + 8 * s, 4);   // 4 producer warps
            mbar_init(mb_empty + 8 * s, 8);   // 8 consumer warps
        }
    }
    __syncthreads();

    if (wid < 8) {
        // ================= consumer =================
        const int wm = wid >> 1, wn = wid & 1;
        const int grp = lane >> 2, qid = lane & 3;
        uint32_t aoff[2], boff[2];
#pragma unroll
        for (int mt = 0; mt < 2; mt++)
            aoff[mt] = (wm * 32 + mt * 16 + (lane & 15)) * ALDR + ((lane & 16) ? 16 : 0);
#pragma unroll
        for (int nb = 0; nb < 2; nb++)
            boff[nb] = (lane & 15) * GBR + (wn * 32 + nb * 16) * 2 + ((lane & 16) ? 16 : 0);

        float cg[2][4][4], cu[2][4][4];
#pragma unroll
        for (int mt = 0; mt < 2; mt++)
#pragma unroll
            for (int nt = 0; nt < 4; nt++)
#pragma unroll
                for (int i = 0; i < 4; i++) { cg[mt][nt][i] = 0.0f; cu[mt][nt][i] = 0.0f; }

        int s = 0, ph = 0;
        for (int c = 0; c < 32; c++) {
            mbar_wait(mb_full + 8 * s, ph);
            const uint32_t Ab = sbase + s * GU_STAGE;
            const uint32_t Gb = Ab + GU_BG;
            const uint32_t Ub = Ab + GU_BU;
#pragma unroll
            for (int ks = 0; ks < 2; ks++) {     // two k16 steps
                uint32_t a[2][4];
                ldsm4(a[0], Ab + aoff[0] + ks * 32);
                ldsm4(a[1], Ab + aoff[1] + ks * 32);
#pragma unroll
                for (int nb = 0; nb < 2; nb++) {
                    uint32_t bg[4], bu[4];
                    ldsm4t(bg, Gb + boff[nb] + ks * 16 * GBR);
                    mma16(cg[0][nb * 2 + 0], a[0], &bg[0]);
                    mma16(cg[0][nb * 2 + 1], a[0], &bg[2]);
                    mma16(cg[1][nb * 2 + 0], a[1], &bg[0]);
                    mma16(cg[1][nb * 2 + 1], a[1], &bg[2]);
                    ldsm4t(bu, Ub + boff[nb] + ks * 16 * GBR);
                    mma16(cu[0][nb * 2 + 0], a[0], &bu[0]);
                    mma16(cu[0][nb * 2 + 1], a[0], &bu[2]);
                    mma16(cu[1][nb * 2 + 0], a[1], &bu[0]);
                    mma16(cu[1][nb * 2 + 1], a[1], &bu[2]);
                }
            }
            __syncwarp();
            if (lane == 0) mbar_arrive(mb_empty + 8 * s);
            if (++s == NSTAGE) { s = 0; ph ^= 1; }
        }

        // epilogue: silu(g)*u
#pragma unroll
        for (int mt = 0; mt < 2; mt++) {
#pragma unroll
            for (int half = 0; half < 2; half++) {
                int m = m0 + wm * 32 + mt * 16 + grp + half * 8;
                if (m >= M) continue;
                float* orow = GATHER ? &g_act[e][m][0] : &g_sact[m][0];
#pragma unroll
                for (int nt = 0; nt < 4; nt++) {
                    int c0 = n0 + wn * 32 + nt * 8 + 2 * qid;
                    float g0 = cg[mt][nt][half * 2 + 0], u0 = cu[mt][nt][half * 2 + 0];
                    float g1 = cg[mt][nt][half * 2 + 1], u1 = cu[mt][nt][half * 2 + 1];
                    float2 o;
                    o.x = (g0 / (1.0f + expf(-g0))) * u0;
                    o.y = (g1 / (1.0f + expf(-g1))) * u1;
                    *(float2*)&orow[c0] = o;
                }
            }
        }
    } else {
        // ================= producer =================
        const int ptid = tid - 256;          // 0..127
        const int base = ptid >> 2;          // 0..31
        const int q    = ptid & 3;
        const int akof = q * 8;              // A col offset (floats)

        const float* ap[4];
#pragma unroll
        for (int i = 0; i < 4; i++) {
            int r = m0 + base + 32 * i;
            if (r < M) {
                int tok = GATHER ? g_tok[e][r] : r;
                ap[i] = X + (size_t)tok * HH + akof;
            } else ap[i] = nullptr;
        }
        const float* gptr = Wg_all + (GATHER ? (size_t)e * HH * FF : 0)
                            + (size_t)base * FF + n0 + q * 4;
        const float* uptr = Wu_all + (GATHER ? (size_t)e * HH * FF : 0)
                            + (size_t)base * FF + n0 + q * 4;

        int s = 0, ph = 1;   // first empty-wait passes immediately
        for (int c = 0; c < 32; c++) {
            const int kk = c * 32;
            float4 av[4][2], gv[4], uv[4];
#pragma unroll
            for (int i = 0; i < 4; i++) {
                av[i][0] = ap[i] ? *(const float4*)(ap[i] + kk)     : make_float4(0,0,0,0);
                av[i][1] = ap[i] ? *(const float4*)(ap[i] + kk + 4) : make_float4(0,0,0,0);
            }
#pragma unroll
            for (int i = 0; i < 4; i++) {
                gv[i] = *(const float4*)(gptr + (size_t)kk * FF + i * 16);
                uv[i] = *(const float4*)(uptr + (size_t)kk * FF + i * 16);
            }
            mbar_wait(mb_empty + 8 * s, ph);
            char* Ast = smem + s * GU_STAGE;
#pragma unroll
            for (int i = 0; i < 4; i++) {
                int row = base + 32 * i;
                *(uint4*)(Ast + row * ALDR + q * 16) = cvt8(av[i][0], av[i][1]);
            }
            char* Gst = Ast + GU_BG;
            char* Ust = Ast + GU_BU;
#pragma unroll
            for (int i = 0; i < 4; i++) {
                uint32_t off = (uint32_t)base * GBR + q * 8 + i * 32;
                *(uint2*)(Gst + off) = cvt4h(gv[i]);
                *(uint2*)(Ust + off) = cvt4h(uv[i]);
            }
            __syncwarp();
            if (lane == 0) mbar_arrive(mb_full + 8 * s);
            if (++s == NSTAGE) { s = 0; ph ^= 1; }
        }
    }
}

// ---------------- down-proj GEMM: fp16 mma, warp-specialized, 4 stages -----
// Block 128(M) x 128(N). Consumers 4M x 2N, warp tile 32x64.
template <bool EXPERT>
__global__ __launch_bounds__(384, 1)
void gemm_down(const float* __restrict__ Wd_all,
               float* __restrict__ out) {
    const int e  = EXPERT ? blockIdx.z : 0;
    const int M  = EXPERT ? g_cnt[e] : TT;
    const int m0 = blockIdx.y * 128;
    if (m0 >= M) return;
    const int n0 = blockIdx.x * 128;

    extern __shared__ char smem[];
    const uint32_t sbase = smem_u32(smem);
    const int tid = threadIdx.x;
    const int wid = tid >> 5, lane = tid & 31;

    const uint32_t mb_full  = sbase + DN_MBAR;
    const uint32_t mb_empty = sbase + DN_MBAR + 32;
    if (tid == 0) {
#pragma unroll
        for (int s = 0; s < NSTAGE; s++) {
            mbar_init(mb_full  + 8 * s, 4);
            mbar_init(mb_empty + 8 * s, 8);
        }
    }
    __syncthreads();

    const float* Asrc = EXPERT ? &g_act[e][0][0] : &g_sact[0][0];

    if (wid < 8) {
        // ================= consumer =================
        const int wm = wid >> 1, wn = wid & 1;
        const int grp = lane >> 2, qid = lane & 3;
        uint32_t aoff[2], boff[4];
#pragma unroll
        for (int mt = 0; mt < 2; mt++)
            aoff[mt] = (wm * 32 + mt * 16 + (lane & 15)) * ALDR + ((lane & 16) ? 16 : 0);
#pragma unroll
        for (int nb = 0; nb < 4; nb++)
            boff[nb] = (lane & 15) * DBR + (wn * 64 + nb * 16) * 2 + ((lane & 16) ? 16 : 0);

        float cc[2][8][4];
#pragma unroll
        for (int mt = 0; mt < 2; mt++)
#pragma unroll
            for (int nt = 0; nt < 8; nt++)
#pragma unroll
                for (int i = 0; i < 4; i++) cc[mt][nt][i] = 0.0f;

        int s = 0, ph = 0;
        for (int c = 0; c < 32; c++) {
            mbar_wait(mb_full + 8 * s, ph);
            const uint32_t Ab = sbase + s * DN_STAGE;
            const uint32_t Bb = Ab + DN_B;
#pragma unroll
            for (int ks = 0; ks < 2; ks++) {
                uint32_t a[2][4];
                ldsm4(a[0], Ab + aoff[0] + ks * 32);
                ldsm4(a[1], Ab + aoff[1] + ks * 32);
#pragma unroll
                for (int nb = 0; nb < 4; nb++) {
                    uint32_t b_[4];
                    ldsm4t(b_, Bb + boff[nb] + ks * 16 * DBR);
                    mma16(cc[0][nb * 2 + 0], a[0], &b_[0]);
                    mma16(cc[0][nb * 2 + 1], a[0], &b_[2]);
                    mma16(cc[1][nb * 2 + 0], a[1], &b_[0]);
                    mma16(cc[1][nb * 2 + 1], a[1], &b_[2]);
                }
            }
            __syncwarp();
            if (lane == 0) mbar_arrive(mb_empty + 8 * s);
            if (++s == NSTAGE) { s = 0; ph ^= 1; }
        }

#pragma unroll
        for (int mt = 0; mt < 2; mt++) {
#pragma unroll
            for (int half = 0; half < 2; half++) {
                int m = m0 + wm * 32 + mt * 16 + grp + half * 8;
                if (m >= M) continue;
                if (EXPERT) {
                    int tok = g_tok[e][m];
                    float w = g_wt[e][m];
                    float* orow = out + (size_t)tok * HH;
#pragma unroll
                    for (int nt = 0; nt < 8; nt++) {
                        int c0 = n0 + wn * 64 + nt * 8 + 2 * qid;
                        atomicAdd(&orow[c0],     w * cc[mt][nt][half * 2 + 0]);
                        atomicAdd(&orow[c0 + 1], w * cc[mt][nt][half * 2 + 1]);
                    }
                } else {
                    float* orow = out + (size_t)m * HH;
#pragma unroll
                    for (int nt = 0; nt < 8; nt++) {
                        int c0 = n0 + wn * 64 + nt * 8 + 2 * qid;
                        float2 o = make_float2(cc[mt][nt][half * 2 + 0],
                                               cc[mt][nt][half * 2 + 1]);
                        *(float2*)&orow[c0] = o;
                    }
                }
            }
        }
    } else {
        // ================= producer =================
        const int ptid = tid - 256;
        const int base = ptid >> 2;
        const int q    = ptid & 3;
        const int akof = q * 8;

        const float* ap[4];
#pragma unroll
        for (int i = 0; i < 4; i++) {
            int r = m0 + base + 32 * i;
            ap[i] = (r < M) ? (Asrc + (size_t)r * FF + akof) : nullptr;
        }
        const float* wptr = Wd_all + (EXPERT ? (size_t)e * FF * HH : 0)
                            + (size_t)base * HH + n0 + q * 4;

        int s = 0, ph = 1;
        for (int c = 0; c < 32; c++) {
            const int kk = c * 32;
            float4 av[4][2], bv[8];
#pragma unroll
            for (int i = 0; i < 4; i++) {
                av[i][0] = ap[i] ? *(const float4*)(ap[i] + kk)     : make_float4(0,0,0,0);
                av[i][1] = ap[i] ? *(const float4*)(ap[i] + kk + 4) : make_float4(0,0,0,0);
            }
#pragma unroll
            for (int i = 0; i < 8; i++)
                bv[i] = *(const float4*)(wptr + (size_t)kk * HH + i * 16);

            mbar_wait(mb_empty + 8 * s, ph);
            char* Ast = smem + s * DN_STAGE;
#pragma unroll
            for (int i = 0; i < 4; i++) {
                int row = base + 32 * i;
                *(uint4*)(Ast + row * ALDR + q * 16) = cvt8(av[i][0], av[i][1]);
            }
            char* Bst = Ast + DN_B;
#pragma unroll
            for (int i = 0; i < 8; i++) {
                uint32_t off = (uint32_t)base * DBR + q * 8 + i * 32;
                *(uint2*)(Bst + off) = cvt4h(bv[i]);
            }
            __syncwarp();
            if (lane == 0) mbar_arrive(mb_full + 8 * s);
            if (++s == NSTAGE) { s = 0; ph ^= 1; }
        }
    }
}

// ---------------- launch ---------------------------------------------------
extern "C" void kernel_launch(void* const* d_in, const int* in_sizes, int n_in,
                              void* d_out, int out_size) {
    const float* x   = (const float*)d_in[0];
    const float* wg  = (const float*)d_in[1];
    const float* wgp = (const float*)d_in[2];
    const float* wup = (const float*)d_in[3];
    const float* wdp = (const float*)d_in[4];
    const float* wsg = (const float*)d_in[5];
    const float* wsu = (const float*)d_in[6];
    const float* wsd = (const float*)d_in[7];
    float* out = (float*)d_out;

    cudaFuncSetAttribute(gemm_gateup<false>, cudaFuncAttributeMaxDynamicSharedMemorySize, GU_BYTES);
    cudaFuncSetAttribute(gemm_gateup<true>,  cudaFuncAttributeMaxDynamicSharedMemorySize, GU_BYTES);
    cudaFuncSetAttribute(gemm_down<false>,   cudaFuncAttributeMaxDynamicSharedMemorySize, DN_BYTES);
    cudaFuncSetAttribute(gemm_down<true>,    cudaFuncAttributeMaxDynamicSharedMemorySize, DN_BYTES);

    int tail = out_size - TT * HH;
    int init_n = (tail > EE ? tail : EE);
    init_kernel<<<(init_n + 255) / 256, 256>>>(out, out_size);

    router_kernel<<<TT / 8, 256>>>(x, wg);

    dim3 gs1(FF / 64, TT / 128, 1);
    gemm_gateup<false><<<gs1, 384, GU_BYTES>>>(x, wsg, wsu);

    dim3 ge1(FF / 64, TT / 128, EE);
    gemm_gateup<true><<<ge1, 384, GU_BYTES>>>(x, wgp, wup);

    dim3 gs2(HH / 128, TT / 128, 1);
    gemm_down<false><<<gs2, 384, DN_BYTES>>>(wsd, out);   // plain store: initializes out

    dim3 ge2(HH / 128, TT / 128, EE);
    gemm_down<true><<<ge2, 384, DN_BYTES>>>(wdp, out);    // weighted atomicAdd combine
}